// round 7
// baseline (speedup 1.0000x reference)
#include <cuda_runtime.h>
#include <cuda_fp16.h>

#define NUM_USERS 80000
#define NUM_ITEMS 40000
#define NUM_NODES 120000
#define RPN       (NUM_NODES + 1)
#define DIM       64
#define NE        (NUM_NODES * DIM)     // 7,680,000
#define NE4       (NE / 4)              // 1,920,000
#define NU4       (NUM_USERS * DIM / 4) // 1,280,000
#define ALPHA     0.8f
#define MAX_EPATH 2000000

// ---------------- scratch (device globals; zero-initialized .bss) ----------
__device__ __align__(256) __half2 g_hin[NE / 2];  // fp16 [user_emb; item_emb]
__device__ __align__(256) __half2 g_h0[NE / 2];   // e0 (fp16)
__device__ __align__(256) __half2 g_h1[NE / 2];   // e1 (fp16)
__device__ __align__(256) __half2 g_h2[NE / 2];   // e2 (fp16)
__device__ __align__(256) float   g_softv[MAX_EPATH];
__device__ __align__(256) int     g_rp_pos[RPN];
__device__ __align__(256) int     g_rp_neg[RPN];
__device__ __align__(256) int     g_rp_path[RPN];
__device__ __align__(256) float   g_thetaw[8];

// ---------------- fused prologue: cvt fp32->fp16 + theta softmax -----------
__global__ __launch_bounds__(256) void k_prologue(
    const float4* __restrict__ U, const float4* __restrict__ I,
    __half2* __restrict__ H,
    const float* __restrict__ theta, float* __restrict__ tw, int n_theta)
{
    int i = blockIdx.x * blockDim.x + threadIdx.x;
    if (i < NE4) {
        float4 v = (i < NU4) ? U[i] : I[i - NU4];
        H[2 * i]     = __floats2half2_rn(v.x, v.y);
        H[2 * i + 1] = __floats2half2_rn(v.z, v.w);
    }
    if (i == 0) {
        float m = -1e30f;
        for (int k = 0; k < n_theta; k++) m = fmaxf(m, theta[k]);
        float s = 0.f; float w[8];
        for (int k = 0; k < n_theta; k++) { w[k] = expf(theta[k] - m); s += w[k]; }
        for (int k = 0; k < n_theta; k++) tw[k] = w[k] / s;
    }
}

// ---------------- row pointers via binary search (rows sorted) --------------
__device__ __forceinline__ int lb(const int* __restrict__ a, int n, int key)
{
    int lo = 0, hi = n;
    while (lo < hi) {
        int mid = (lo + hi) >> 1;
        if (a[mid] < key) lo = mid + 1; else hi = mid;
    }
    return lo;
}

__global__ __launch_bounds__(256) void k_rowptr(
    const int* __restrict__ pr, int np,
    const int* __restrict__ nr, int nn,
    const int* __restrict__ qr, int nq,
    int* __restrict__ rp_p, int* __restrict__ rp_n, int* __restrict__ rp_q)
{
    int r = blockIdx.x * blockDim.x + threadIdx.x;
    if (r >= RPN) return;
    rp_p[r] = lb(pr, np, r);
    rp_n[r] = lb(nr, nn, r);
    rp_q[r] = lb(qr, nq, r);
}

// ---------------- path edge weights: ev = exp(counts @ theta_w) -------------
// 2 edges per thread -> 3 aligned LDG.128, no smem, no atomics.
__global__ __launch_bounds__(256) void k_path_ev(
    const float* __restrict__ p_counts, const float* __restrict__ tw,
    float* __restrict__ softv, int n)
{
    const int t = blockIdx.x * blockDim.x + threadIdx.x;
    const int e0 = 2 * t;
    if (e0 >= n) return;
    const float w0 = tw[0], w1 = tw[1], w2 = tw[2],
                w3 = tw[3], w4 = tw[4], w5 = tw[5];
    const float4* src = (const float4*)(p_counts + (size_t)e0 * 6);
    float4 a = src[0];
    float4 b = src[1];
    float4 c = src[2];
    float v0 = a.x * w0;
    v0 = fmaf(a.y, w1, v0); v0 = fmaf(a.z, w2, v0);
    v0 = fmaf(a.w, w3, v0); v0 = fmaf(b.x, w4, v0);
    v0 = fmaf(b.y, w5, v0);
    float ev0 = expf(v0);
    if (e0 + 1 < n) {
        float v1 = b.z * w0;
        v1 = fmaf(b.w, w1, v1); v1 = fmaf(c.x, w2, v1);
        v1 = fmaf(c.y, w3, v1); v1 = fmaf(c.z, w4, v1);
        v1 = fmaf(c.w, w5, v1);
        *(float2*)(softv + e0) = make_float2(ev0, expf(v1));
    } else {
        softv[e0] = ev0;
    }
}

// ---------------- CSR gather-accumulate over one row's edge range -----------
// 8-lane quarter per row; lane owns 8 dims (one LDG.128 of fp16 per edge).
// Depth-1 prefetch of the gathered row.
__device__ __forceinline__ void gather_accum(
    const int* __restrict__ cols, const float* __restrict__ vals,
    int b, int e, float scale, const uint4* __restrict__ X, int ql,
    float acc[8])
{
    if (b >= e) return;
    int   c = __ldg(cols + b);
    float v = __ldg(vals + b);
    uint4 hv = X[(size_t)c * 8 + ql];
    for (int j = b; j < e; j++) {
        int cn = c; float vn = v; uint4 hvn = hv;
        if (j + 1 < e) {
            cn  = __ldg(cols + j + 1);
            vn  = __ldg(vals + j + 1);
            hvn = X[(size_t)cn * 8 + ql];
        }
        float f = v * scale;
        float2 p0 = __half22float2(*(const __half2*)&hv.x);
        float2 p1 = __half22float2(*(const __half2*)&hv.y);
        float2 p2 = __half22float2(*(const __half2*)&hv.z);
        float2 p3 = __half22float2(*(const __half2*)&hv.w);
        acc[0] = fmaf(f, p0.x, acc[0]); acc[1] = fmaf(f, p0.y, acc[1]);
        acc[2] = fmaf(f, p1.x, acc[2]); acc[3] = fmaf(f, p1.y, acc[3]);
        acc[4] = fmaf(f, p2.x, acc[4]); acc[5] = fmaf(f, p2.y, acc[5]);
        acc[6] = fmaf(f, p3.x, acc[6]); acc[7] = fmaf(f, p3.y, acc[7]);
        c = cn; v = vn; hv = hvn;
    }
}

__device__ __forceinline__ uint4 pack8(const float acc[8])
{
    uint4 o;
    *(__half2*)&o.x = __floats2half2_rn(acc[0], acc[1]);
    *(__half2*)&o.y = __floats2half2_rn(acc[2], acc[3]);
    *(__half2*)&o.z = __floats2half2_rn(acc[4], acc[5]);
    *(__half2*)&o.w = __floats2half2_rn(acc[6], acc[7]);
    return o;
}

// ---------------- path CSR SpMM: e0 = softmax-normalized gather -> H0 -------
__global__ __launch_bounds__(256) void k_spmm_path_csr(
    const int* __restrict__ rp, const int* __restrict__ cols,
    const float* __restrict__ ev, const uint4* __restrict__ X,
    uint4* __restrict__ H0)
{
    const int ql = threadIdx.x & 7;
    const int r  = blockIdx.x * 32 + (threadIdx.x >> 3);
    if (r >= NUM_NODES) return;
    const int b = rp[r], e = rp[r + 1];

    float s = 0.f;
    for (int j = b; j < e; j++) s += __ldg(ev + j);
    const float inv = 1.f / (s + 1e-12f);

    float acc[8];
    #pragma unroll
    for (int k = 0; k < 8; k++) acc[k] = 0.f;
    gather_accum(cols, ev, b, e, inv, X, ql, acc);
    H0[(size_t)r * 8 + ql] = pack8(acc);
}

// ---------------- fused layer: e_new = pos - a*neg + a*e_old ----------------
// FINAL=false: write Hnew fp16. FINAL=true: out = (H0+H1+H2+e_new)/4 fp32.
template<bool FINAL>
__global__ __launch_bounds__(256) void k_layer_csr(
    const int* __restrict__ rp_pos, const int* __restrict__ pcol,
    const float* __restrict__ pval,
    const int* __restrict__ rp_neg, const int* __restrict__ ncol,
    const float* __restrict__ nval,
    const uint4* __restrict__ X,        // gather table == e_old
    const uint4* __restrict__ H0, const uint4* __restrict__ H1,  // FINAL only
    uint4* __restrict__ Hnew, float4* __restrict__ out)
{
    const int ql = threadIdx.x & 7;
    const int r  = blockIdx.x * 32 + (threadIdx.x >> 3);
    if (r >= NUM_NODES) return;

    float acc[8];
    #pragma unroll
    for (int k = 0; k < 8; k++) acc[k] = 0.f;
    gather_accum(pcol, pval, rp_pos[r], rp_pos[r + 1],  1.0f,  X, ql, acc);
    gather_accum(ncol, nval, rp_neg[r], rp_neg[r + 1], -ALPHA, X, ql, acc);

    const size_t ri = (size_t)r * 8 + ql;
    uint4 ho = X[ri];
    float2 q0 = __half22float2(*(const __half2*)&ho.x);
    float2 q1 = __half22float2(*(const __half2*)&ho.y);
    float2 q2 = __half22float2(*(const __half2*)&ho.z);
    float2 q3 = __half22float2(*(const __half2*)&ho.w);
    float en[8];
    en[0] = fmaf(ALPHA, q0.x, acc[0]); en[1] = fmaf(ALPHA, q0.y, acc[1]);
    en[2] = fmaf(ALPHA, q1.x, acc[2]); en[3] = fmaf(ALPHA, q1.y, acc[3]);
    en[4] = fmaf(ALPHA, q2.x, acc[4]); en[5] = fmaf(ALPHA, q2.y, acc[5]);
    en[6] = fmaf(ALPHA, q3.x, acc[6]); en[7] = fmaf(ALPHA, q3.y, acc[7]);

    if (!FINAL) {
        Hnew[ri] = pack8(en);
    } else {
        uint4 a4 = H0[ri];
        uint4 b4 = H1[ri];
        float2 a0 = __half22float2(*(const __half2*)&a4.x);
        float2 a1 = __half22float2(*(const __half2*)&a4.y);
        float2 a2 = __half22float2(*(const __half2*)&a4.z);
        float2 a3 = __half22float2(*(const __half2*)&a4.w);
        float2 b0 = __half22float2(*(const __half2*)&b4.x);
        float2 b1 = __half22float2(*(const __half2*)&b4.y);
        float2 b2 = __half22float2(*(const __half2*)&b4.z);
        float2 b3 = __half22float2(*(const __half2*)&b4.w);
        float4 o0, o1;
        o0.x = (a0.x + b0.x + q0.x + en[0]) * 0.25f;
        o0.y = (a0.y + b0.y + q0.y + en[1]) * 0.25f;
        o0.z = (a1.x + b1.x + q1.x + en[2]) * 0.25f;
        o0.w = (a1.y + b1.y + q1.y + en[3]) * 0.25f;
        o1.x = (a2.x + b2.x + q2.x + en[4]) * 0.25f;
        o1.y = (a2.y + b2.y + q2.y + en[5]) * 0.25f;
        o1.z = (a3.x + b3.x + q3.x + en[6]) * 0.25f;
        o1.w = (a3.y + b3.y + q3.y + en[7]) * 0.25f;
        out[(size_t)r * 16 + ql * 2]     = o0;
        out[(size_t)r * 16 + ql * 2 + 1] = o1;
    }
}

// ---------------------------------------------------------------------------
extern "C" void kernel_launch(void* const* d_in, const int* in_sizes, int n_in,
                              void* d_out, int out_size)
{
    const float* user_emb = (const float*)d_in[0];
    const float* item_emb = (const float*)d_in[1];
    const float* theta    = (const float*)d_in[2];
    const int*   pos_row  = (const int*)d_in[3];
    const int*   pos_col  = (const int*)d_in[4];
    const float* pos_val  = (const float*)d_in[5];
    const int*   neg_row  = (const int*)d_in[6];
    const int*   neg_col  = (const int*)d_in[7];
    const float* neg_val  = (const float*)d_in[8];
    const int*   p_row    = (const int*)d_in[9];
    const int*   p_col    = (const int*)d_in[10];
    const float* p_counts = (const float*)d_in[11];

    const int n_pos  = in_sizes[3];
    const int n_neg  = in_sizes[6];
    int n_path = in_sizes[9];
    if (n_path > MAX_EPATH) n_path = MAX_EPATH;
    const int n_theta = in_sizes[2] < 8 ? in_sizes[2] : 8;

    float *psv, *ptw;
    int *rpp, *rpn, *rpq;
    __half2 *hin, *h0, *h1, *h2;
    cudaGetSymbolAddress((void**)&hin, g_hin);
    cudaGetSymbolAddress((void**)&h0,  g_h0);
    cudaGetSymbolAddress((void**)&h1,  g_h1);
    cudaGetSymbolAddress((void**)&h2,  g_h2);
    cudaGetSymbolAddress((void**)&psv, g_softv);
    cudaGetSymbolAddress((void**)&rpp, g_rp_pos);
    cudaGetSymbolAddress((void**)&rpn, g_rp_neg);
    cudaGetSymbolAddress((void**)&rpq, g_rp_path);
    cudaGetSymbolAddress((void**)&ptw, g_thetaw);

    const int TB = 256;
    const int row_grid = (NUM_NODES + 31) / 32;   // 3750 blocks, quarter per row

    // prologue: fp16 input table + theta softmax
    k_prologue<<<(NE4 + TB - 1) / TB, TB>>>((const float4*)user_emb,
                                            (const float4*)item_emb, hin,
                                            theta, ptw, n_theta);

    // row pointers for all 3 edge lists (rows sorted by construction)
    k_rowptr<<<(RPN + TB - 1) / TB, TB>>>(pos_row, n_pos, neg_row, n_neg,
                                          p_row, n_path, rpp, rpn, rpq);

    // path edge weights ev = exp(counts @ theta_w)
    {
        int pairs = (n_path + 1) / 2;
        k_path_ev<<<(pairs + TB - 1) / TB, TB>>>(p_counts, ptw, psv, n_path);
    }

    // e0: per-row softmax-normalized path gather -> H0
    k_spmm_path_csr<<<row_grid, TB>>>(rpq, p_col, psv, (const uint4*)hin,
                                      (uint4*)h0);

    // layer 1: H1 = pos(H0) - a*neg(H0) + a*H0
    k_layer_csr<false><<<row_grid, TB>>>(rpp, pos_col, pos_val,
                                         rpn, neg_col, neg_val,
                                         (const uint4*)h0, nullptr, nullptr,
                                         (uint4*)h1, nullptr);
    // layer 2
    k_layer_csr<false><<<row_grid, TB>>>(rpp, pos_col, pos_val,
                                         rpn, neg_col, neg_val,
                                         (const uint4*)h1, nullptr, nullptr,
                                         (uint4*)h2, nullptr);
    // layer 3 fused with final mean -> d_out
    k_layer_csr<true><<<row_grid, TB>>>(rpp, pos_col, pos_val,
                                        rpn, neg_col, neg_val,
                                        (const uint4*)h2,
                                        (const uint4*)h0, (const uint4*)h1,
                                        nullptr, (float4*)d_out);
}